// round 14
// baseline (speedup 1.0000x reference)
#include <cuda_runtime.h>
#include <cuda_fp16.h>
#include <cstdint>

// ---------------------------------------------------------------------------
// Problem constants
// ---------------------------------------------------------------------------
#define HDIM    512
#define BATCH   32
#define SEQ     2048
#define M_TOTAL (BATCH * SEQ)    // 65536
#define K_TOTAL 1024
#define WROW    1536             // W_attn row stride in floats

// GEMM tiling (fp16 mma m16n8k16): one 512-thread CTA per SM (R8 config)
#define BM 128
#define BN 256
#define BK 64
#define NSTG 4
#define NKI (K_TOTAL / BK)       // 16
#define NTHR 512
#define KPAD 72                  // padded smem row stride (halves) -> 144 B
#define A_BYTES (BM * KPAD * 2)  // 18432
#define B_BYTES (BN * KPAD * 2)  // 36864
#define STAGE_B (A_BYTES + B_BYTES)       // 55296
#define EPI_OFF (NSTG * STAGE_B)          // 221184: epilogue region after stages
#define SMEM_BYTES (EPI_OFF + 4608)       // 225792 (< 227 KB opt-in)

// Batch-chunked convert->GEMM pipeline: {12, 20}
#define CH0 12
#define CH1 20

// ---------------------------------------------------------------------------
// Device scratch (static: no runtime allocation; zero-initialized at load)
// ---------------------------------------------------------------------------
__device__ __half g_ench[(size_t)M_TOTAL * K_TOTAL];  // compacted fp16 active rows per batch
__device__ __half g_wh[HDIM * K_TOTAL];               // fp16 packed W_e [512][1024]
__device__ float  g_c[BATCH * HDIM];                  // state_proj + b_attn
__device__ float  g_part[2][M_TOTAL];                 // partial scores per n-tile (orig positions)
__device__ int    g_idx[M_TOTAL];                     // per-batch compacted seq indices
__device__ int    g_cnt[BATCH];                       // active count per batch

// ---------------------------------------------------------------------------
// Helpers
// ---------------------------------------------------------------------------
__device__ __forceinline__ void cp_async16(uint32_t dst_smem, const void* src) {
    asm volatile("cp.async.cg.shared.global [%0], [%1], 16;"
                 :: "r"(dst_smem), "l"(src));
}
#define CP_COMMIT() asm volatile("cp.async.commit_group;" ::: "memory")
#define CP_WAIT(n)  asm volatile("cp.async.wait_group %0;" :: "n"(n) : "memory")

#define LDSM_X4(r0, r1, r2, r3, addr)                                          \
    asm volatile("ldmatrix.sync.aligned.m8n8.x4.shared.b16 {%0,%1,%2,%3}, [%4];" \
                 : "=r"(r0), "=r"(r1), "=r"(r2), "=r"(r3) : "r"(addr))

__device__ __forceinline__ void mma_f16(float d[4], const uint32_t a[4], const uint32_t b[2]) {
    asm volatile(
        "mma.sync.aligned.m16n8k16.row.col.f32.f16.f16.f32 "
        "{%0,%1,%2,%3}, {%4,%5,%6,%7}, {%8,%9}, {%0,%1,%2,%3};"
        : "+f"(d[0]), "+f"(d[1]), "+f"(d[2]), "+f"(d[3])
        : "r"(a[0]), "r"(a[1]), "r"(a[2]), "r"(a[3]), "r"(b[0]), "r"(b[1]));
}

__device__ __forceinline__ uint32_t pack_h2(float x, float y) {
    __half2 h = __floats2half2_rn(x, y);
    return *reinterpret_cast<uint32_t*>(&h);
}

// Accurate fast tanh via MUFU.EX2: abs err ~1e-6
__device__ __forceinline__ float tanh_fast(float x) {
    x = fminf(fmaxf(x, -15.f), 15.f);
    float t = 2.885390081777927f * x;   // 2*log2(e)*x
    float e;
    asm("ex2.approx.f32 %0, %1;" : "=f"(e) : "f"(t));
    return (e - 1.f) / (e + 1.f);
}

// ---------------------------------------------------------------------------
// Kernel 0: per-batch compaction of unmasked positions (deterministic scan)
// ---------------------------------------------------------------------------
__global__ void __launch_bounds__(1024) compact_kernel(const int* __restrict__ mask) {
    __shared__ int sc[1024];
    const int b = blockIdx.x;
    const int t = threadIdx.x;
    const int m0 = mask[b * SEQ + 2 * t] != 0;
    const int m1 = mask[b * SEQ + 2 * t + 1] != 0;
    int s = m0 + m1;
    sc[t] = s;
    __syncthreads();
#pragma unroll
    for (int off = 1; off < 1024; off <<= 1) {
        int v = (t >= off) ? sc[t - off] : 0;
        __syncthreads();
        sc[t] += v;
        __syncthreads();
    }
    const int excl = sc[t] - s;
    if (m0) g_idx[b * SEQ + excl] = 2 * t;
    if (m1) g_idx[b * SEQ + excl + m0] = 2 * t + 1;
    if (t == 1023) g_cnt[b] = sc[1023];
}

// ---------------------------------------------------------------------------
// Kernel A: convert + compact active rows (fp32 -> fp16), warp-per-row.
// Grid (SEQ/8, nbatch); batch = b_base + blockIdx.y.
// ---------------------------------------------------------------------------
__global__ void __launch_bounds__(256) convert_active_kernel(const float* __restrict__ enc,
                                                             int b_base) {
    const int b = b_base + blockIdx.y;
    const int w = threadIdx.x >> 5;
    const int l = threadIdx.x & 31;
    const int j = blockIdx.x * 8 + w;
    if (j >= g_cnt[b]) return;
    const int s = g_idx[b * SEQ + j];
    const float4* src = reinterpret_cast<const float4*>(enc + ((size_t)b * SEQ + s) * K_TOTAL);
    uint4* dst = reinterpret_cast<uint4*>(g_ench + ((size_t)b * SEQ + j) * K_TOTAL);
#pragma unroll
    for (int o = 0; o < 4; o++) {
        const int c = l + o * 32;
        float4 f0 = src[2 * c];
        float4 f1 = src[2 * c + 1];
        uint4 p;
        p.x = pack_h2(f0.x, f0.y);
        p.y = pack_h2(f0.z, f0.w);
        p.z = pack_h2(f1.x, f1.y);
        p.w = pack_h2(f1.z, f1.w);
        dst[c] = p;
    }
}

// Kernel B: convert + pack W_e: W_attn[:, 512:1536] -> g_wh[512][1024]
__global__ void __launch_bounds__(256) convert_w_kernel(const float* __restrict__ W) {
    int r = blockIdx.x;
    int t = threadIdx.x;
    const float4 f = *reinterpret_cast<const float4*>(W + (size_t)r * WROW + HDIM + t * 4);
    uint2 packed;
    packed.x = pack_h2(f.x, f.y);
    packed.y = pack_h2(f.z, f.w);
    reinterpret_cast<uint2*>(g_wh)[r * 256 + t] = packed;
}

// ---------------------------------------------------------------------------
// Kernel C: c[b,h] = sum_k output[b,k] * W_attn[h,k] + b_attn[h]  (fp32)
// ---------------------------------------------------------------------------
__global__ void __launch_bounds__(HDIM) cproj_kernel(const float* __restrict__ outp,
                                                     const float* __restrict__ W,
                                                     const float* __restrict__ b_attn) {
    __shared__ float so[HDIM];
    int b = blockIdx.x;
    int h = threadIdx.x;
    so[h] = outp[b * HDIM + h];
    __syncthreads();
    const float4* wrow = reinterpret_cast<const float4*>(W + (size_t)h * WROW);
    float acc = 0.f;
#pragma unroll 8
    for (int k4 = 0; k4 < HDIM / 4; k4++) {
        float4 w = wrow[k4];
        acc += w.x * so[k4 * 4 + 0] + w.y * so[k4 * 4 + 1] +
               w.z * so[k4 * 4 + 2] + w.w * so[k4 * 4 + 3];
    }
    g_c[b * HDIM + h] = acc + b_attn[h];
}

// ---------------------------------------------------------------------------
// Kernel D: fused fp16 GEMM (mma.sync m16n8k16) + tanh + v-dot epilogue
// over the COMPACTED active rows of one batch-chunk.
// Grid: (2 n-tiles, 16 m-tiles, nbatch); batch = b_base + blockIdx.z.
// Epilogue inputs (c, v, sidx) live in a dedicated smem region loaded BEFORE
// the mainloop (no post-loop smem reuse or extra sync on the tail).
// ---------------------------------------------------------------------------
__global__ void __launch_bounds__(NTHR, 1)
gemm_tanh_kernel(const float* __restrict__ v_g, int b_base) {
    const int bb  = b_base + blockIdx.z;
    const int cnt = g_cnt[bb];
    if ((int)blockIdx.y * BM >= cnt) return;   // whole-CTA uniform early exit

    extern __shared__ char smc[];
    const int tid  = threadIdx.x;
    const int wid  = tid >> 5;
    const int lane = tid & 31;
    const int g    = lane >> 2;
    const int tg   = lane & 3;
    const int wm   = wid & 3;
    const int wn   = wid >> 2;
    const int n0   = blockIdx.x * BN;
    const int m0   = bb * SEQ + blockIdx.y * BM;   // compacted row base

    const uint32_t sbase = (uint32_t)__cvta_generic_to_shared(smc);

    // Epilogue smem region (separate from pipeline stages)
    float* c_sm = reinterpret_cast<float*>(smc + EPI_OFF);          // [256]
    float* v_sm = c_sm + BN;                                        // [256]
    int*   sidx = reinterpret_cast<int*>(v_sm + BN);                // [128]
    float* red  = reinterpret_cast<float*>(sidx + BM);              // [4][128]

    if (tid < BN) {
        c_sm[tid] = g_c[bb * HDIM + n0 + tid];
        v_sm[tid] = v_g[n0 + tid];
    }
    if (tid < BM) {
        const int j = blockIdx.y * BM + tid;
        sidx[tid] = (j < cnt) ? g_idx[bb * SEQ + j] : -1;
    }
    // (mainloop __syncthreads ordering makes these visible before the epilogue)

    const int a_row = lane & 15;
    const int a_k   = (lane >> 4) * 8;
    const int b_row = (lane & 7) + ((lane >> 4) & 1) * 8;
    const int b_k   = ((lane >> 3) & 1) * 8;

    float acc[2][8][4];
#pragma unroll
    for (int mt = 0; mt < 2; mt++)
#pragma unroll
        for (int nt = 0; nt < 8; nt++)
#pragma unroll
            for (int r = 0; r < 4; r++) acc[mt][nt][r] = 0.f;

    auto load_stage = [&](int s, int kb) {
        const int kbase = kb * BK;
        const uint32_t as = sbase + (uint32_t)(s * STAGE_B);
        const uint32_t bs = as + A_BYTES;
#pragma unroll
        for (int i = 0; i < 2; i++) {           // A: 128 rows x 8 chunks = 1024
            int c = tid + i * NTHR;
            int r = c >> 3, ch = c & 7;
            cp_async16(as + (uint32_t)(r * KPAD + ch * 8) * 2u,
                       g_ench + (size_t)(m0 + r) * K_TOTAL + kbase + ch * 8);
        }
#pragma unroll
        for (int i = 0; i < 4; i++) {           // B: 256 rows x 8 chunks = 2048
            int c = tid + i * NTHR;
            int r = c >> 3, ch = c & 7;
            cp_async16(bs + (uint32_t)(r * KPAD + ch * 8) * 2u,
                       g_wh + (size_t)(n0 + r) * K_TOTAL + kbase + ch * 8);
        }
    };

#pragma unroll
    for (int s = 0; s < NSTG - 1; s++) {
        load_stage(s, s);
        CP_COMMIT();
    }

    for (int i = 0; i < NKI; i++) {
        CP_WAIT(NSTG - 2);
        __syncthreads();
        if (i + NSTG - 1 < NKI) load_stage((i + NSTG - 1) % NSTG, i + NSTG - 1);
        CP_COMMIT();

        const uint32_t aS = sbase + (uint32_t)((i % NSTG) * STAGE_B);
        const uint32_t bS = aS + A_BYTES;

#pragma unroll
        for (int ks = 0; ks < 4; ks++) {
            const int k0 = ks * 16;
            uint32_t af[2][4], bfr[4][4];
#pragma unroll
            for (int mt = 0; mt < 2; mt++) {
                uint32_t addr = aS + (uint32_t)((wm * 32 + mt * 16 + a_row) * KPAD + k0 + a_k) * 2u;
                LDSM_X4(af[mt][0], af[mt][1], af[mt][2], af[mt][3], addr);
            }
#pragma unroll
            for (int np = 0; np < 4; np++) {
                uint32_t addr = bS + (uint32_t)((wn * 64 + np * 16 + b_row) * KPAD + k0 + b_k) * 2u;
                LDSM_X4(bfr[np][0], bfr[np][1], bfr[np][2], bfr[np][3], addr);
            }
#pragma unroll
            for (int mt = 0; mt < 2; mt++)
#pragma unroll
                for (int nt = 0; nt < 8; nt++)
                    mma_f16(acc[mt][nt], af[mt], &bfr[nt >> 1][(nt & 1) * 2]);
        }
    }

    // Epilogue: tanh + v-dot, quad-reduce within warp, per-wn partial into smem
#pragma unroll
    for (int mt = 0; mt < 2; mt++) {
        float s0 = 0.f, s1 = 0.f;
#pragma unroll
        for (int nt = 0; nt < 8; nt++) {
            const int nl = wn * 64 + nt * 8 + 2 * tg;
            const float c0 = c_sm[nl], c1 = c_sm[nl + 1];
            const float w0 = v_sm[nl], w1 = v_sm[nl + 1];
            s0 = fmaf(w0, tanh_fast(acc[mt][nt][0] + c0), s0);
            s0 = fmaf(w1, tanh_fast(acc[mt][nt][1] + c1), s0);
            s1 = fmaf(w0, tanh_fast(acc[mt][nt][2] + c0), s1);
            s1 = fmaf(w1, tanh_fast(acc[mt][nt][3] + c1), s1);
        }
        s0 += __shfl_xor_sync(0xffffffffu, s0, 1);
        s0 += __shfl_xor_sync(0xffffffffu, s0, 2);
        s1 += __shfl_xor_sync(0xffffffffu, s1, 1);
        s1 += __shfl_xor_sync(0xffffffffu, s1, 2);
        if (tg == 0) {
            const int rloc = wm * 32 + mt * 16 + g;
            red[wn * BM + rloc]     = s0;
            red[wn * BM + rloc + 8] = s1;
        }
    }
    __syncthreads();

    if (tid < BM) {
        const int s = sidx[tid];
        if (s >= 0) {
            float sum = red[tid] + red[BM + tid] + red[2 * BM + tid] + red[3 * BM + tid];
            g_part[blockIdx.x][bb * SEQ + s] = sum;
        }
    }
}

// ---------------------------------------------------------------------------
// Kernel E: masked softmax over S per batch row.
// Masked positions output exactly 0 (matches fp32 underflow in the reference).
// ---------------------------------------------------------------------------
__global__ void __launch_bounds__(256) softmax_kernel(const int* __restrict__ mask,
                                                      float* __restrict__ out) {
    __shared__ float red[256];
    const int b = blockIdx.x;
    const int t = threadIdx.x;
    float vals[SEQ / 256];
    bool  live[SEQ / 256];
    float mx = -3.4e38f;
#pragma unroll
    for (int i = 0; i < SEQ / 256; i++) {
        const int idx = b * SEQ + t + i * 256;
        const bool m = (mask[idx] != 0);
        live[i] = m;
        float sc = m ? (g_part[0][idx] + g_part[1][idx]) : -3.4e38f;
        vals[i] = sc;
        mx = fmaxf(mx, sc);
    }
    red[t] = mx;
    __syncthreads();
    for (int o = 128; o > 0; o >>= 1) {
        if (t < o) red[t] = fmaxf(red[t], red[t + o]);
        __syncthreads();
    }
    mx = red[0];
    __syncthreads();
    float sum = 0.f;
#pragma unroll
    for (int i = 0; i < SEQ / 256; i++) {
        vals[i] = live[i] ? expf(vals[i] - mx) : 0.f;
        sum += vals[i];
    }
    red[t] = sum;
    __syncthreads();
    for (int o = 128; o > 0; o >>= 1) {
        if (t < o) red[t] += red[t + o];
        __syncthreads();
    }
    const float inv = 1.f / red[0];
#pragma unroll
    for (int i = 0; i < SEQ / 256; i++) {
        out[b * SEQ + t + i * 256] = vals[i] * inv;
    }
}

// ---------------------------------------------------------------------------
// Host launcher: {12,20} convert->GEMM pipeline, GEMM sequential on one stream.
// ---------------------------------------------------------------------------
extern "C" void kernel_launch(void* const* d_in, const int* in_sizes, int n_in,
                              void* d_out, int out_size) {
    const float* outp = (const float*)d_in[0];   // (32, 512)
    const float* enc  = (const float*)d_in[1];   // (32, 2048, 1024)
    const int*   mask = (const int*)d_in[2];     // (32, 2048)
    const float* W    = (const float*)d_in[3];   // (512, 1536)
    const float* ba   = (const float*)d_in[4];   // (512,)
    const float* v    = (const float*)d_in[5];   // (512,)

    static cudaStream_t s1 = nullptr, s2 = nullptr;
    static cudaEvent_t ev0 = nullptr, evC, evA0, evA1, evG;
    if (!s1) {
        cudaFuncSetAttribute(gemm_tanh_kernel,
                             cudaFuncAttributeMaxDynamicSharedMemorySize, SMEM_BYTES);
        cudaStreamCreateWithFlags(&s1, cudaStreamNonBlocking);
        cudaStreamCreateWithFlags(&s2, cudaStreamNonBlocking);
        cudaEventCreateWithFlags(&ev0, cudaEventDisableTiming);
        cudaEventCreateWithFlags(&evC, cudaEventDisableTiming);
        cudaEventCreateWithFlags(&evA0, cudaEventDisableTiming);
        cudaEventCreateWithFlags(&evA1, cudaEventDisableTiming);
        cudaEventCreateWithFlags(&evG, cudaEventDisableTiming);
    }

    // Fork: side streams wait on prior capture-stream state before reading inputs
    cudaEventRecord(ev0, 0);
    cudaStreamWaitEvent(s1, ev0, 0);
    cudaStreamWaitEvent(s2, ev0, 0);

    compact_kernel<<<BATCH, 1024>>>(mask);               // capture stream
    convert_w_kernel<<<HDIM, 256, 0, s1>>>(W);           // side stream 1 (GEMM stream)
    cproj_kernel<<<BATCH, HDIM, 0, s2>>>(outp, W, ba);   // side stream 2
    cudaEventRecord(evC, s2);
    cudaStreamWaitEvent(s1, evC, 0);                     // GEMM stream needs g_c too

    // Convert chunks on the capture stream (after compact)
    convert_active_kernel<<<dim3(SEQ / 8, CH0), 256>>>(enc, 0);
    cudaEventRecord(evA0, 0);
    convert_active_kernel<<<dim3(SEQ / 8, CH1), 256>>>(enc, CH0);
    cudaEventRecord(evA1, 0);

    // GEMM chunks sequential on s1, each gated on its convert
    cudaStreamWaitEvent(s1, evA0, 0);
    gemm_tanh_kernel<<<dim3(HDIM / BN, SEQ / BM, CH0), NTHR, SMEM_BYTES, s1>>>(v, 0);
    cudaStreamWaitEvent(s1, evA1, 0);
    gemm_tanh_kernel<<<dim3(HDIM / BN, SEQ / BM, CH1), NTHR, SMEM_BYTES, s1>>>(v, CH0);
    cudaEventRecord(evG, s1);

    // Join and finish
    cudaStreamWaitEvent(0, evG, 0);
    softmax_kernel<<<BATCH, 256>>>(mask, (float*)d_out);
}

// round 15
// speedup vs baseline: 1.1865x; 1.1865x over previous
#include <cuda_runtime.h>
#include <cuda_fp16.h>
#include <cstdint>

// ---------------------------------------------------------------------------
// Problem constants
// ---------------------------------------------------------------------------
#define HDIM    512
#define BATCH   32
#define SEQ     2048
#define M_TOTAL (BATCH * SEQ)    // 65536
#define K_TOTAL 1024
#define WROW    1536             // W_attn row stride in floats

// GEMM tiling (fp16 mma m16n8k16): one 512-thread CTA per SM (R8 config)
#define BM 128
#define BN 256
#define BK 64
#define NSTG 4
#define NKI (K_TOTAL / BK)       // 16
#define NTHR 512
#define KPAD 72                  // padded smem row stride (halves) -> 144 B
#define A_BYTES (BM * KPAD * 2)  // 18432
#define B_BYTES (BN * KPAD * 2)  // 36864
#define STAGE_B (A_BYTES + B_BYTES)       // 55296
#define EPI_OFF (NSTG * STAGE_B)          // 221184: epilogue region after stages
#define SMEM_BYTES (EPI_OFF + 4608)       // 225792

// ---------------------------------------------------------------------------
// Device scratch (static: no runtime allocation; zero-initialized at load)
// ---------------------------------------------------------------------------
__device__ __half g_ench[(size_t)M_TOTAL * K_TOTAL];  // compacted fp16 active rows per batch
__device__ __half g_wh[HDIM * K_TOTAL];               // fp16 packed W_e [512][1024]
__device__ float  g_c[BATCH * HDIM];                  // state_proj + b_attn
__device__ float  g_part[2][M_TOTAL];                 // partial scores per n-tile (orig positions)
__device__ int    g_idx[M_TOTAL];                     // per-batch compacted seq indices
__device__ int    g_cnt[BATCH];                       // active count per batch

// ---------------------------------------------------------------------------
// Helpers
// ---------------------------------------------------------------------------
__device__ __forceinline__ void cp_async16(uint32_t dst_smem, const void* src) {
    asm volatile("cp.async.cg.shared.global [%0], [%1], 16;"
                 :: "r"(dst_smem), "l"(src));
}
#define CP_COMMIT() asm volatile("cp.async.commit_group;" ::: "memory")
#define CP_WAIT(n)  asm volatile("cp.async.wait_group %0;" :: "n"(n) : "memory")

#define LDSM_X4(r0, r1, r2, r3, addr)                                          \
    asm volatile("ldmatrix.sync.aligned.m8n8.x4.shared.b16 {%0,%1,%2,%3}, [%4];" \
                 : "=r"(r0), "=r"(r1), "=r"(r2), "=r"(r3) : "r"(addr))

__device__ __forceinline__ void mma_f16(float d[4], const uint32_t a[4], const uint32_t b[2]) {
    asm volatile(
        "mma.sync.aligned.m16n8k16.row.col.f32.f16.f16.f32 "
        "{%0,%1,%2,%3}, {%4,%5,%6,%7}, {%8,%9}, {%0,%1,%2,%3};"
        : "+f"(d[0]), "+f"(d[1]), "+f"(d[2]), "+f"(d[3])
        : "r"(a[0]), "r"(a[1]), "r"(a[2]), "r"(a[3]), "r"(b[0]), "r"(b[1]));
}

__device__ __forceinline__ uint32_t pack_h2(float x, float y) {
    __half2 h = __floats2half2_rn(x, y);
    return *reinterpret_cast<uint32_t*>(&h);
}

// Accurate fast tanh via MUFU.EX2: abs err ~1e-6
__device__ __forceinline__ float tanh_fast(float x) {
    x = fminf(fmaxf(x, -15.f), 15.f);
    float t = 2.885390081777927f * x;   // 2*log2(e)*x
    float e;
    asm("ex2.approx.f32 %0, %1;" : "=f"(e) : "f"(t));
    return (e - 1.f) / (e + 1.f);
}

// ---------------------------------------------------------------------------
// Kernel 0: per-batch compaction of unmasked positions (deterministic scan)
// ---------------------------------------------------------------------------
__global__ void __launch_bounds__(1024) compact_kernel(const int* __restrict__ mask) {
    __shared__ int sc[1024];
    const int b = blockIdx.x;
    const int t = threadIdx.x;
    const int m0 = mask[b * SEQ + 2 * t] != 0;
    const int m1 = mask[b * SEQ + 2 * t + 1] != 0;
    int s = m0 + m1;
    sc[t] = s;
    __syncthreads();
#pragma unroll
    for (int off = 1; off < 1024; off <<= 1) {
        int v = (t >= off) ? sc[t - off] : 0;
        __syncthreads();
        sc[t] += v;
        __syncthreads();
    }
    const int excl = sc[t] - s;
    if (m0) g_idx[b * SEQ + excl] = 2 * t;
    if (m1) g_idx[b * SEQ + excl + m0] = 2 * t + 1;
    if (t == 1023) g_cnt[b] = sc[1023];
}

// ---------------------------------------------------------------------------
// Kernel A: convert + compact active rows (fp32 -> fp16), warp-per-row.
// Grid (SEQ/8, BATCH), 256 threads (8 warps); warp w handles active row
// j = blockIdx.x*8 + w. Each lane: 4 independent 16B output chunks (8 LDG.128).
// ---------------------------------------------------------------------------
__global__ void __launch_bounds__(256) convert_active_kernel(const float* __restrict__ enc) {
    const int b = blockIdx.y;
    const int w = threadIdx.x >> 5;
    const int l = threadIdx.x & 31;
    const int j = blockIdx.x * 8 + w;
    if (j >= g_cnt[b]) return;
    const int s = g_idx[b * SEQ + j];
    const float4* src = reinterpret_cast<const float4*>(enc + ((size_t)b * SEQ + s) * K_TOTAL);
    uint4* dst = reinterpret_cast<uint4*>(g_ench + ((size_t)b * SEQ + j) * K_TOTAL);
#pragma unroll
    for (int o = 0; o < 4; o++) {
        const int c = l + o * 32;              // 16B output chunk index (0..127)
        float4 f0 = src[2 * c];
        float4 f1 = src[2 * c + 1];
        uint4 p;
        p.x = pack_h2(f0.x, f0.y);
        p.y = pack_h2(f0.z, f0.w);
        p.z = pack_h2(f1.x, f1.y);
        p.w = pack_h2(f1.z, f1.w);
        dst[c] = p;
    }
}

// Kernel B: convert + pack W_e: W_attn[:, 512:1536] -> g_wh[512][1024]
__global__ void __launch_bounds__(256) convert_w_kernel(const float* __restrict__ W) {
    int r = blockIdx.x;
    int t = threadIdx.x;
    const float4 f = *reinterpret_cast<const float4*>(W + (size_t)r * WROW + HDIM + t * 4);
    uint2 packed;
    packed.x = pack_h2(f.x, f.y);
    packed.y = pack_h2(f.z, f.w);
    reinterpret_cast<uint2*>(g_wh)[r * 256 + t] = packed;
}

// ---------------------------------------------------------------------------
// Kernel C: c[b,h] = sum_k output[b,k] * W_attn[h,k] + b_attn[h]  (fp32)
// ---------------------------------------------------------------------------
__global__ void __launch_bounds__(HDIM) cproj_kernel(const float* __restrict__ outp,
                                                     const float* __restrict__ W,
                                                     const float* __restrict__ b_attn) {
    __shared__ float so[HDIM];
    int b = blockIdx.x;
    int h = threadIdx.x;
    so[h] = outp[b * HDIM + h];
    __syncthreads();
    const float4* wrow = reinterpret_cast<const float4*>(W + (size_t)h * WROW);
    float acc = 0.f;
#pragma unroll 8
    for (int k4 = 0; k4 < HDIM / 4; k4++) {
        float4 w = wrow[k4];
        acc += w.x * so[k4 * 4 + 0] + w.y * so[k4 * 4 + 1] +
               w.z * so[k4 * 4 + 2] + w.w * so[k4 * 4 + 3];
    }
    g_c[b * HDIM + h] = acc + b_attn[h];
}

// ---------------------------------------------------------------------------
// Kernel D: fused fp16 GEMM (mma.sync m16n8k16) + tanh + v-dot epilogue
// over the COMPACTED active rows of one batch.
// Grid: (2 n-tiles, 16 m-tiles, 32 batches); CTAs past the active count exit.
// Epilogue inputs (c, v, sidx) live in a dedicated smem region loaded BEFORE
// the mainloop; no post-loop CP_WAIT or extra sync on the critical tail.
// ---------------------------------------------------------------------------
__global__ void __launch_bounds__(NTHR, 1)
gemm_tanh_kernel(const float* __restrict__ v_g) {
    const int bb  = blockIdx.z;
    const int cnt = g_cnt[bb];
    if ((int)blockIdx.y * BM >= cnt) return;   // whole-CTA uniform early exit

    extern __shared__ char smc[];
    const int tid  = threadIdx.x;
    const int wid  = tid >> 5;
    const int lane = tid & 31;
    const int g    = lane >> 2;
    const int tg   = lane & 3;
    const int wm   = wid & 3;
    const int wn   = wid >> 2;
    const int n0   = blockIdx.x * BN;
    const int m0   = bb * SEQ + blockIdx.y * BM;   // compacted row base

    const uint32_t sbase = (uint32_t)__cvta_generic_to_shared(smc);

    // Epilogue smem region (separate from pipeline stages)
    float* c_sm = reinterpret_cast<float*>(smc + EPI_OFF);          // [256]
    float* v_sm = c_sm + BN;                                        // [256]
    int*   sidx = reinterpret_cast<int*>(v_sm + BN);                // [128]
    float* red  = reinterpret_cast<float*>(sidx + BM);              // [4][128]

    if (tid < BN) {
        c_sm[tid] = g_c[bb * HDIM + n0 + tid];
        v_sm[tid] = v_g[n0 + tid];
    }
    if (tid < BM) {
        const int j = blockIdx.y * BM + tid;
        sidx[tid] = (j < cnt) ? g_idx[bb * SEQ + j] : -1;
    }
    // (visibility to the epilogue is guaranteed by the mainloop __syncthreads)

    const int a_row = lane & 15;
    const int a_k   = (lane >> 4) * 8;
    const int b_row = (lane & 7) + ((lane >> 4) & 1) * 8;
    const int b_k   = ((lane >> 3) & 1) * 8;

    float acc[2][8][4];
#pragma unroll
    for (int mt = 0; mt < 2; mt++)
#pragma unroll
        for (int nt = 0; nt < 8; nt++)
#pragma unroll
            for (int r = 0; r < 4; r++) acc[mt][nt][r] = 0.f;

    auto load_stage = [&](int s, int kb) {
        const int kbase = kb * BK;
        const uint32_t as = sbase + (uint32_t)(s * STAGE_B);
        const uint32_t bs = as + A_BYTES;
#pragma unroll
        for (int i = 0; i < 2; i++) {           // A: 128 rows x 8 chunks = 1024
            int c = tid + i * NTHR;
            int r = c >> 3, ch = c & 7;
            cp_async16(as + (uint32_t)(r * KPAD + ch * 8) * 2u,
                       g_ench + (size_t)(m0 + r) * K_TOTAL + kbase + ch * 8);
        }
#pragma unroll
        for (int i = 0; i < 4; i++) {           // B: 256 rows x 8 chunks = 2048
            int c = tid + i * NTHR;
            int r = c >> 3, ch = c & 7;
            cp_async16(bs + (uint32_t)(r * KPAD + ch * 8) * 2u,
                       g_wh + (size_t)(n0 + r) * K_TOTAL + kbase + ch * 8);
        }
    };

#pragma unroll
    for (int s = 0; s < NSTG - 1; s++) {
        load_stage(s, s);
        CP_COMMIT();
    }

    for (int i = 0; i < NKI; i++) {
        CP_WAIT(NSTG - 2);
        __syncthreads();
        if (i + NSTG - 1 < NKI) load_stage((i + NSTG - 1) % NSTG, i + NSTG - 1);
        CP_COMMIT();

        const uint32_t aS = sbase + (uint32_t)((i % NSTG) * STAGE_B);
        const uint32_t bS = aS + A_BYTES;

#pragma unroll
        for (int ks = 0; ks < 4; ks++) {
            const int k0 = ks * 16;
            uint32_t af[2][4], bfr[4][4];
#pragma unroll
            for (int mt = 0; mt < 2; mt++) {
                uint32_t addr = aS + (uint32_t)((wm * 32 + mt * 16 + a_row) * KPAD + k0 + a_k) * 2u;
                LDSM_X4(af[mt][0], af[mt][1], af[mt][2], af[mt][3], addr);
            }
#pragma unroll
            for (int np = 0; np < 4; np++) {
                uint32_t addr = bS + (uint32_t)((wn * 64 + np * 16 + b_row) * KPAD + k0 + b_k) * 2u;
                LDSM_X4(bfr[np][0], bfr[np][1], bfr[np][2], bfr[np][3], addr);
            }
#pragma unroll
            for (int mt = 0; mt < 2; mt++)
#pragma unroll
                for (int nt = 0; nt < 8; nt++)
                    mma_f16(acc[mt][nt], af[mt], &bfr[nt >> 1][(nt & 1) * 2]);
        }
    }

    // Epilogue: tanh + v-dot, quad-reduce within warp, per-wn partial into smem
#pragma unroll
    for (int mt = 0; mt < 2; mt++) {
        float s0 = 0.f, s1 = 0.f;
#pragma unroll
        for (int nt = 0; nt < 8; nt++) {
            const int nl = wn * 64 + nt * 8 + 2 * tg;
            const float c0 = c_sm[nl], c1 = c_sm[nl + 1];
            const float w0 = v_sm[nl], w1 = v_sm[nl + 1];
            s0 = fmaf(w0, tanh_fast(acc[mt][nt][0] + c0), s0);
            s0 = fmaf(w1, tanh_fast(acc[mt][nt][1] + c1), s0);
            s1 = fmaf(w0, tanh_fast(acc[mt][nt][2] + c0), s1);
            s1 = fmaf(w1, tanh_fast(acc[mt][nt][3] + c1), s1);
        }
        s0 += __shfl_xor_sync(0xffffffffu, s0, 1);
        s0 += __shfl_xor_sync(0xffffffffu, s0, 2);
        s1 += __shfl_xor_sync(0xffffffffu, s1, 1);
        s1 += __shfl_xor_sync(0xffffffffu, s1, 2);
        if (tg == 0) {
            const int rloc = wm * 32 + mt * 16 + g;
            red[wn * BM + rloc]     = s0;
            red[wn * BM + rloc + 8] = s1;
        }
    }
    __syncthreads();

    if (tid < BM) {
        const int s = sidx[tid];
        if (s >= 0) {
            float sum = red[tid] + red[BM + tid] + red[2 * BM + tid] + red[3 * BM + tid];
            g_part[blockIdx.x][bb * SEQ + s] = sum;
        }
    }
}

// ---------------------------------------------------------------------------
// Kernel E: masked softmax over S per batch row.
// Masked positions output exactly 0 (matches fp32 underflow in the reference).
// ---------------------------------------------------------------------------
__global__ void __launch_bounds__(256) softmax_kernel(const int* __restrict__ mask,
                                                      float* __restrict__ out) {
    __shared__ float red[256];
    const int b = blockIdx.x;
    const int t = threadIdx.x;
    float vals[SEQ / 256];
    bool  live[SEQ / 256];
    float mx = -3.4e38f;
#pragma unroll
    for (int i = 0; i < SEQ / 256; i++) {
        const int idx = b * SEQ + t + i * 256;
        const bool m = (mask[idx] != 0);
        live[i] = m;
        float sc = m ? (g_part[0][idx] + g_part[1][idx]) : -3.4e38f;
        vals[i] = sc;
        mx = fmaxf(mx, sc);
    }
    red[t] = mx;
    __syncthreads();
    for (int o = 128; o > 0; o >>= 1) {
        if (t < o) red[t] = fmaxf(red[t], red[t + o]);
        __syncthreads();
    }
    mx = red[0];
    __syncthreads();
    float sum = 0.f;
#pragma unroll
    for (int i = 0; i < SEQ / 256; i++) {
        vals[i] = live[i] ? expf(vals[i] - mx) : 0.f;
        sum += vals[i];
    }
    red[t] = sum;
    __syncthreads();
    for (int o = 128; o > 0; o >>= 1) {
        if (t < o) red[t] += red[t + o];
        __syncthreads();
    }
    const float inv = 1.f / red[0];
#pragma unroll
    for (int i = 0; i < SEQ / 256; i++) {
        out[b * SEQ + t + i * 256] = vals[i] * inv;
    }
}

// ---------------------------------------------------------------------------
// Host launcher: R12 structure — prep kernels forked, big kernels monolithic.
// ---------------------------------------------------------------------------
extern "C" void kernel_launch(void* const* d_in, const int* in_sizes, int n_in,
                              void* d_out, int out_size) {
    const float* outp = (const float*)d_in[0];   // (32, 512)
    const float* enc  = (const float*)d_in[1];   // (32, 2048, 1024)
    const int*   mask = (const int*)d_in[2];     // (32, 2048)
    const float* W    = (const float*)d_in[3];   // (512, 1536)
    const float* ba   = (const float*)d_in[4];   // (512,)
    const float* v    = (const float*)d_in[5];   // (512,)

    static cudaStream_t s1 = nullptr, s2 = nullptr;
    static cudaEvent_t ev0 = nullptr, ev1, ev2;
    if (!s1) {
        cudaFuncSetAttribute(gemm_tanh_kernel,
                             cudaFuncAttributeMaxDynamicSharedMemorySize, SMEM_BYTES);
        cudaStreamCreateWithFlags(&s1, cudaStreamNonBlocking);
        cudaStreamCreateWithFlags(&s2, cudaStreamNonBlocking);
        cudaEventCreateWithFlags(&ev0, cudaEventDisableTiming);
        cudaEventCreateWithFlags(&ev1, cudaEventDisableTiming);
        cudaEventCreateWithFlags(&ev2, cudaEventDisableTiming);
    }

    // Fork: side streams must wait on prior capture-stream work before reading inputs
    cudaEventRecord(ev0, 0);
    cudaStreamWaitEvent(s1, ev0, 0);
    cudaStreamWaitEvent(s2, ev0, 0);

    compact_kernel<<<BATCH, 1024>>>(mask);               // capture stream
    convert_w_kernel<<<HDIM, 256, 0, s1>>>(W);           // side stream 1
    cproj_kernel<<<BATCH, HDIM, 0, s2>>>(outp, W, ba);   // side stream 2

    // convert_active depends on compact (same stream order)
    convert_active_kernel<<<dim3(SEQ / 8, BATCH), 256>>>(enc);

    // Join side streams before the GEMM
    cudaEventRecord(ev1, s1);
    cudaEventRecord(ev2, s2);
    cudaStreamWaitEvent(0, ev1, 0);
    cudaStreamWaitEvent(0, ev2, 0);

    gemm_tanh_kernel<<<dim3(HDIM / BN, SEQ / BM, BATCH), NTHR, SMEM_BYTES>>>(v);
    softmax_kernel<<<BATCH, 256>>>(mask, (float*)d_out);
}